// round 16
// baseline (speedup 1.0000x reference)
#include <cuda_runtime.h>
#include <cuda_bf16.h>
#include <cstdint>

// ---------------------------------------------------------------------------
// Problem constants
// ---------------------------------------------------------------------------
#define EMBED  1024
#define SEQ    4096
#define BATCH  4
#define NHEADS 16
#define HDIM   64
#define MTOT   (BATCH * SEQ)   // 16384
#define KV_CHUNKS 8
#define KV_CLEN   (SEQ / KV_CHUNKS)   // 512

// GEMM tiling: BM=128, BN=128, BK=32, mma.sync m16n8k16, double-buffered
#define BM 128
#define BN 128
#define BK 32
#define ROW_ELEMS (BK + 8)            // 40 bf16 (16B pad) -> stride 80B
#define RBYTES    (ROW_ELEMS * 2)     // 80
#define TILE_B    (BM * RBYTES)       // 10240 bytes per tile
#define BUF_B     (4 * TILE_B)        // Ah, Al, Bh, Bl = 40960
#define GEMM_SMEM (2 * BUF_B)         // 81920 bytes

// ---------------------------------------------------------------------------
// sm_80-era primitives only (harness compiles PTX at .target sm_103, which
// rejects all tcgen05/TMEM instructions -- verified by R6 ptxas failure).
// ---------------------------------------------------------------------------
__device__ __forceinline__ uint32_t smem_to_u32(const void* p) {
    uint32_t a;
    asm("{ .reg .u64 t; cvta.to.shared.u64 t, %1; cvt.u32.u64 %0, t; }" : "=r"(a) : "l"(p));
    return a;
}

__device__ __forceinline__ void cp_async16(uint32_t saddr, const void* gaddr) {
    asm volatile("cp.async.cg.shared.global [%0], [%1], 16;" :: "r"(saddr), "l"(gaddr));
}

__device__ __forceinline__ uint32_t lds_u32(uint32_t addr) {
    uint32_t v;
    asm volatile("ld.shared.b32 %0, [%1];" : "=r"(v) : "r"(addr));
    return v;
}

// D += A * B   (m16n8k16, bf16 inputs, f32 accumulate)
__device__ __forceinline__ void mma16816(float* c, const uint32_t* a, const uint32_t* b) {
    asm volatile(
        "mma.sync.aligned.m16n8k16.row.col.f32.bf16.bf16.f32 "
        "{%0,%1,%2,%3}, {%4,%5,%6,%7}, {%8,%9}, {%0,%1,%2,%3};"
        : "+f"(c[0]), "+f"(c[1]), "+f"(c[2]), "+f"(c[3])
        : "r"(a[0]), "r"(a[1]), "r"(a[2]), "r"(a[3]), "r"(b[0]), "r"(b[1]));
}

// ---------------------------------------------------------------------------
// Device-global scratch (allocation-free rule: static globals only)
// ---------------------------------------------------------------------------
__device__ __nv_bfloat16 g_xh[MTOT * EMBED];
__device__ __nv_bfloat16 g_xl[MTOT * EMBED];
__device__ __nv_bfloat16 g_Wh[4][EMBED * EMBED];   // q,k,v,o
__device__ __nv_bfloat16 g_Wl[4][EMBED * EMBED];
__device__ float g_qphi[MTOT * EMBED];
__device__ float g_kphi[MTOT * EMBED];
__device__ float g_v[MTOT * EMBED];
__device__ float g_KVp[BATCH * NHEADS * KV_CHUNKS * HDIM * HDIM];
__device__ float g_Ksp[BATCH * NHEADS * KV_CHUNKS * HDIM];
__device__ float g_KV[BATCH * NHEADS * HDIM * HDIM];
__device__ float g_Ks[BATCH * NHEADS * HDIM];
__device__ __nv_bfloat16 g_ah[MTOT * EMBED];
__device__ __nv_bfloat16 g_al[MTOT * EMBED];

// ---------------------------------------------------------------------------
// fp32 -> (hi, lo) bf16 split, vectorized x4
// ---------------------------------------------------------------------------
__device__ __forceinline__ void split4(const float4 xv, uint2& ho, uint2& lo_) {
    float f[4] = {xv.x, xv.y, xv.z, xv.w};
    __nv_bfloat16 h[4], l[4];
#pragma unroll
    for (int m = 0; m < 4; ++m) {
        h[m] = __float2bfloat16(f[m]);
        l[m] = __float2bfloat16(f[m] - __bfloat162float(h[m]));
    }
    ho  = *reinterpret_cast<uint2*>(h);
    lo_ = *reinterpret_cast<uint2*>(l);
}

__global__ void split_kernel(const float4* __restrict__ src,
                             uint2* __restrict__ hi, uint2* __restrict__ lo, int n4) {
    int i = blockIdx.x * blockDim.x + threadIdx.x;
    if (i >= n4) return;
    uint2 h, l;
    split4(src[i], h, l);
    hi[i] = h;
    lo[i] = l;
}

// Splits all 4 weight matrices in one launch; blockIdx.y selects the matrix.
__global__ void split4_kernel(const float4* __restrict__ s0, const float4* __restrict__ s1,
                              const float4* __restrict__ s2, const float4* __restrict__ s3,
                              uint2* __restrict__ hi, uint2* __restrict__ lo, int n4) {
    int i = blockIdx.x * blockDim.x + threadIdx.x;
    if (i >= n4) return;
    const int w = blockIdx.y;
    const float4* src = (w == 0) ? s0 : (w == 1) ? s1 : (w == 2) ? s2 : s3;
    uint2 h, l;
    split4(src[i], h, l);
    hi[(long)w * n4 + i] = h;
    lo[(long)w * n4 + i] = l;
}

// ---------------------------------------------------------------------------
// Split-bf16 mma.sync GEMM: out[m,n] = sum_k A[m,k]*B[n,k] + bias[n]
// A = Ah+Al, B = Bh+Bl, drop lo*lo. CTA tile 128x128x32, 8 warps,
// warp tile 32(m) x 64(n). cp.async double-buffered SMEM.
// mode 0: phi = elu+1 epilogue; mode 1: linear.
// ---------------------------------------------------------------------------
__global__ __launch_bounds__(256)
void gemm_split_kernel(const __nv_bfloat16* __restrict__ Ah,
                       const __nv_bfloat16* __restrict__ Al,
                       const __nv_bfloat16* __restrict__ Bh,
                       const __nv_bfloat16* __restrict__ Bl,
                       const float* __restrict__ bias,
                       float* __restrict__ out,
                       int mode) {
    extern __shared__ char smem[];
    const uint32_t sb = smem_to_u32(smem);
    const int tid = threadIdx.x;
    const int wid = tid >> 5, lane = tid & 31;
    const int ntile = blockIdx.x, mtile = blockIdx.y;
    const long arow0 = (long)mtile * BM;
    const long brow0 = (long)ntile * BN;
    const int wm = wid & 3, wn = wid >> 2;   // 4 x 2 warp grid
    const int m0 = wm * 32, n0 = wn * 64;

    const __nv_bfloat16* gsrc[4] = {Ah, Al, Bh, Bl};

    float acc[2][8][4];
#pragma unroll
    for (int t = 0; t < 2; ++t)
#pragma unroll
        for (int u = 0; u < 8; ++u)
#pragma unroll
            for (int q = 0; q < 4; ++q) acc[t][u][q] = 0.f;

    auto issue_loads = [&](int buf, int ci) {
        const int k0 = ci * BK;
#pragma unroll
        for (int t = 0; t < 4; ++t) {
            const __nv_bfloat16* g = gsrc[t];
            const long row0 = (t < 2) ? arow0 : brow0;
            const uint32_t sdst = sb + buf * BUF_B + t * TILE_B;
#pragma unroll
            for (int j = 0; j < 2; ++j) {
                int s = tid + 256 * j;          // 0..511
                int r = s >> 2, c16 = s & 3;    // 128 rows x 4 x 16B
                cp_async16(sdst + r * RBYTES + c16 * 16,
                           g + (row0 + r) * EMBED + k0 + c16 * 8);
            }
        }
        asm volatile("cp.async.commit_group;" ::: "memory");
    };

    auto compute = [&](int buf) {
        const uint32_t b0 = sb + buf * BUF_B;
        const int cb = (lane & 3) * 4;          // byte offset of k-pair in row
#pragma unroll
        for (int ks = 0; ks < 2; ++ks) {
            const int kb = ks * 32 + cb;        // 16 elems = 32 bytes per k-step
            uint32_t ah[2][4], al[2][4];
#pragma unroll
            for (int t = 0; t < 2; ++t) {
                const int row = m0 + t * 16 + (lane >> 2);
                const uint32_t rh0 = b0 + row * RBYTES + kb;
                const uint32_t rh1 = b0 + (row + 8) * RBYTES + kb;
                ah[t][0] = lds_u32(rh0);
                ah[t][1] = lds_u32(rh1);
                ah[t][2] = lds_u32(rh0 + 16);
                ah[t][3] = lds_u32(rh1 + 16);
                const uint32_t rl0 = rh0 + TILE_B;
                const uint32_t rl1 = rh1 + TILE_B;
                al[t][0] = lds_u32(rl0);
                al[t][1] = lds_u32(rl1);
                al[t][2] = lds_u32(rl0 + 16);
                al[t][3] = lds_u32(rl1 + 16);
            }
            uint32_t bh[8][2], bl[8][2];
#pragma unroll
            for (int u = 0; u < 8; ++u) {
                const int row = n0 + u * 8 + (lane >> 2);
                const uint32_t rb = b0 + 2 * TILE_B + row * RBYTES + kb;
                bh[u][0] = lds_u32(rb);
                bh[u][1] = lds_u32(rb + 16);
                bl[u][0] = lds_u32(rb + TILE_B);
                bl[u][1] = lds_u32(rb + TILE_B + 16);
            }
            // Three passes over the 16 accumulators: consecutive HMMAs hit
            // distinct acc registers (dependency distance 16, not 1).
#pragma unroll
            for (int t = 0; t < 2; ++t)
#pragma unroll
                for (int u = 0; u < 8; ++u)
                    mma16816(acc[t][u], ah[t], bh[u]);
#pragma unroll
            for (int t = 0; t < 2; ++t)
#pragma unroll
                for (int u = 0; u < 8; ++u)
                    mma16816(acc[t][u], ah[t], bl[u]);
#pragma unroll
            for (int t = 0; t < 2; ++t)
#pragma unroll
                for (int u = 0; u < 8; ++u)
                    mma16816(acc[t][u], al[t], bh[u]);
        }
    };

    issue_loads(0, 0);
#pragma unroll 1
    for (int c = 0; c < EMBED / BK; ++c) {
        if (c + 1 < EMBED / BK) {
            issue_loads((c + 1) & 1, c + 1);
            asm volatile("cp.async.wait_group 1;" ::: "memory");
        } else {
            asm volatile("cp.async.wait_group 0;" ::: "memory");
        }
        __syncthreads();
        compute(c & 1);
        __syncthreads();
    }

    // Epilogue: bias + optional phi, 8B vectorized stores.
#pragma unroll
    for (int t = 0; t < 2; ++t) {
        const long row_a = arow0 + m0 + t * 16 + (lane >> 2);
        const long row_b = row_a + 8;
#pragma unroll
        for (int u = 0; u < 8; ++u) {
            const int col = ntile * BN + n0 + u * 8 + (lane & 3) * 2;
            const float2 bv = *reinterpret_cast<const float2*>(bias + col);
            float v0 = acc[t][u][0] + bv.x;
            float v1 = acc[t][u][1] + bv.y;
            float v2 = acc[t][u][2] + bv.x;
            float v3 = acc[t][u][3] + bv.y;
            if (mode == 0) {
                v0 = (v0 > 0.f) ? (v0 + 1.f) : __expf(v0);
                v1 = (v1 > 0.f) ? (v1 + 1.f) : __expf(v1);
                v2 = (v2 > 0.f) ? (v2 + 1.f) : __expf(v2);
                v3 = (v3 > 0.f) ? (v3 + 1.f) : __expf(v3);
            }
            float2 o01 = {v0, v1}, o23 = {v2, v3};
            *reinterpret_cast<float2*>(out + row_a * EMBED + col) = o01;
            *reinterpret_cast<float2*>(out + row_b * EMBED + col) = o23;
        }
    }
}

// ---------------------------------------------------------------------------
// KV partial: per (chunk, h, b) block accumulates KV[64,64] and Ksum[64]
// over KV_CLEN sequence positions (fp32 SIMT; deterministic, no atomics)
// ---------------------------------------------------------------------------
__global__ __launch_bounds__(256)
void kv_partial_kernel(const float* __restrict__ kphi, const float* __restrict__ v,
                       float* __restrict__ KVp, float* __restrict__ Ksp) {
    __shared__ float ks_[64][64];
    __shared__ float vs_[64][64];
    const int tid = threadIdx.x;
    const int chunk = blockIdx.x, h = blockIdx.y, b = blockIdx.z;
    const int dq = tid >> 4, eq = tid & 15;
    float acc[4][4];
#pragma unroll
    for (int i = 0; i < 4; ++i)
#pragma unroll
        for (int j = 0; j < 4; ++j) acc[i][j] = 0.f;
    float ksum[4] = {0.f, 0.f, 0.f, 0.f};
    const long base = ((long)b * SEQ + chunk * KV_CLEN) * EMBED + h * HDIM;
    for (int s0 = 0; s0 < KV_CLEN; s0 += 64) {
#pragma unroll
        for (int j = 0; j < 4; ++j) {
            int idx = tid + 256 * j;
            int r = idx >> 4, c4 = idx & 15;
            *reinterpret_cast<float4*>(&ks_[r][c4 * 4]) =
                *(reinterpret_cast<const float4*>(kphi + base + (long)(s0 + r) * EMBED) + c4);
            *reinterpret_cast<float4*>(&vs_[r][c4 * 4]) =
                *(reinterpret_cast<const float4*>(v + base + (long)(s0 + r) * EMBED) + c4);
        }
        __syncthreads();
#pragma unroll 2
        for (int ss = 0; ss < 64; ++ss) {
            float4 kk = *reinterpret_cast<float4*>(&ks_[ss][dq * 4]);
            float4 vv = *reinterpret_cast<float4*>(&vs_[ss][eq * 4]);
            float kd[4] = {kk.x, kk.y, kk.z, kk.w};
            float ve[4] = {vv.x, vv.y, vv.z, vv.w};
#pragma unroll
            for (int i = 0; i < 4; ++i) {
#pragma unroll
                for (int j = 0; j < 4; ++j) acc[i][j] += kd[i] * ve[j];
                ksum[i] += kd[i];
            }
        }
        __syncthreads();
    }
    const long ob = (((long)b * NHEADS + h) * KV_CHUNKS + chunk) * (HDIM * HDIM);
#pragma unroll
    for (int i = 0; i < 4; ++i)
#pragma unroll
        for (int j = 0; j < 4; ++j)
            KVp[ob + (dq * 4 + i) * HDIM + eq * 4 + j] = acc[i][j];
    if (eq == 0) {
        const long kb = (((long)b * NHEADS + h) * KV_CHUNKS + chunk) * HDIM;
#pragma unroll
        for (int i = 0; i < 4; ++i) Ksp[kb + dq * 4 + i] = ksum[i];
    }
}

__global__ void kv_reduce_kernel(const float* __restrict__ KVp, const float* __restrict__ Ksp,
                                 float* __restrict__ KV, float* __restrict__ Ks) {
    const int bh = blockIdx.x, tid = threadIdx.x;
    for (int i = tid; i < HDIM * HDIM; i += 256) {
        float s = 0.f;
#pragma unroll
        for (int c = 0; c < KV_CHUNKS; ++c) s += KVp[((long)bh * KV_CHUNKS + c) * (HDIM * HDIM) + i];
        KV[(long)bh * (HDIM * HDIM) + i] = s;
    }
    if (tid < HDIM) {
        float s = 0.f;
#pragma unroll
        for (int c = 0; c < KV_CHUNKS; ++c) s += Ksp[((long)bh * KV_CHUNKS + c) * HDIM + tid];
        Ks[(long)bh * HDIM + tid] = s;
    }
}

// ---------------------------------------------------------------------------
// Attention: out[s,e] = (q_phi[s,:] . KV[:,e]) / (q_phi[s,:] . Ksum + eps)
// 64-row seq tile per block; writes attn as hi/lo bf16 for the final GEMM.
// ---------------------------------------------------------------------------
__global__ __launch_bounds__(256)
void attn_kernel(const float* __restrict__ qphi, const float* __restrict__ KV,
                 const float* __restrict__ Ksum,
                 __nv_bfloat16* __restrict__ ah, __nv_bfloat16* __restrict__ al) {
    __shared__ float qs[64][68];
    __shared__ float kvs[64][64];
    __shared__ float kss[64];
    __shared__ float den[64];
    const int tid = threadIdx.x;
    const int st = blockIdx.x, h = blockIdx.y, b = blockIdx.z;
    const int bh = b * NHEADS + h;
    const long qbase = ((long)b * SEQ + st * 64) * EMBED + h * HDIM;
#pragma unroll
    for (int j = 0; j < 4; ++j) {
        int idx = tid + 256 * j;
        int r = idx >> 4, c4 = idx & 15;
        *reinterpret_cast<float4*>(&qs[r][c4 * 4]) =
            *(reinterpret_cast<const float4*>(qphi + qbase + (long)r * EMBED) + c4);
        *reinterpret_cast<float4*>(&kvs[r][c4 * 4]) =
            *(reinterpret_cast<const float4*>(KV + (long)bh * (HDIM * HDIM) + r * HDIM) + c4);
    }
    if (tid < 64) kss[tid] = Ksum[(long)bh * HDIM + tid];
    __syncthreads();
    if (tid < 64) {
        float s = 0.f;
#pragma unroll 8
        for (int d = 0; d < 64; ++d) s += qs[tid][d] * kss[d];
        den[tid] = s + 1e-6f;
    }
    __syncthreads();
    const int e = tid & 63, g = tid >> 6;
    float acc[16];
#pragma unroll
    for (int r = 0; r < 16; ++r) acc[r] = 0.f;
    for (int d = 0; d < 64; ++d) {
        float kd = kvs[d][e];
#pragma unroll
        for (int r = 0; r < 16; ++r) acc[r] += qs[g * 16 + r][d] * kd;
    }
#pragma unroll
    for (int r = 0; r < 16; ++r) {
        const int sl = g * 16 + r;
        float val = acc[r] / den[sl];
        const long oi = ((long)b * SEQ + st * 64 + sl) * EMBED + h * HDIM + e;
        __nv_bfloat16 hv = __float2bfloat16(val);
        ah[oi] = hv;
        al[oi] = __float2bfloat16(val - __bfloat162float(hv));
    }
}

// ---------------------------------------------------------------------------
// Launch
// ---------------------------------------------------------------------------
extern "C" void kernel_launch(void* const* d_in, const int* in_sizes, int n_in,
                              void* d_out, int out_size) {
    (void)in_sizes; (void)n_in; (void)out_size;
    const float* x  = (const float*)d_in[0];
    const float* Wq = (const float*)d_in[1];
    const float* bq = (const float*)d_in[2];
    const float* Wk = (const float*)d_in[3];
    const float* bk = (const float*)d_in[4];
    const float* Wv = (const float*)d_in[5];
    const float* bv = (const float*)d_in[6];
    const float* Wo = (const float*)d_in[7];
    const float* bo = (const float*)d_in[8];

    void *xh, *xl, *wh, *wl, *qphi, *kphi, *vbuf, *kvp, *ksp, *kv, *ks, *ahp, *alp;
    cudaGetSymbolAddress(&xh, g_xh);   cudaGetSymbolAddress(&xl, g_xl);
    cudaGetSymbolAddress(&wh, g_Wh);   cudaGetSymbolAddress(&wl, g_Wl);
    cudaGetSymbolAddress(&qphi, g_qphi); cudaGetSymbolAddress(&kphi, g_kphi);
    cudaGetSymbolAddress(&vbuf, g_v);
    cudaGetSymbolAddress(&kvp, g_KVp); cudaGetSymbolAddress(&ksp, g_Ksp);
    cudaGetSymbolAddress(&kv, g_KV);   cudaGetSymbolAddress(&ks, g_Ks);
    cudaGetSymbolAddress(&ahp, g_ah);  cudaGetSymbolAddress(&alp, g_al);

    __nv_bfloat16* Whp = (__nv_bfloat16*)wh;
    __nv_bfloat16* Wlp = (__nv_bfloat16*)wl;
    const int WSZ = EMBED * EMBED;

    cudaFuncSetAttribute(gemm_split_kernel, cudaFuncAttributeMaxDynamicSharedMemorySize, GEMM_SMEM);

    // 1) hi/lo splits: x (1 launch), all 4 weights (1 launch)
    {
        int n4 = MTOT * EMBED / 4;
        split_kernel<<<(n4 + 255) / 256, 256>>>((const float4*)x, (uint2*)xh, (uint2*)xl, n4);
        int w4 = WSZ / 4;
        split4_kernel<<<dim3((w4 + 255) / 256, 4), 256>>>(
            (const float4*)Wq, (const float4*)Wk, (const float4*)Wv, (const float4*)Wo,
            (uint2*)wh, (uint2*)wl, w4);
    }

    dim3 ggrid(EMBED / BN, MTOT / BM);   // (8, 128)
    // 2) Q/K/V projections (phi fused for q, k)
    gemm_split_kernel<<<ggrid, 256, GEMM_SMEM>>>((__nv_bfloat16*)xh, (__nv_bfloat16*)xl,
        Whp + 0 * WSZ, Wlp + 0 * WSZ, bq, (float*)qphi, 0);
    gemm_split_kernel<<<ggrid, 256, GEMM_SMEM>>>((__nv_bfloat16*)xh, (__nv_bfloat16*)xl,
        Whp + 1 * WSZ, Wlp + 1 * WSZ, bk, (float*)kphi, 0);
    gemm_split_kernel<<<ggrid, 256, GEMM_SMEM>>>((__nv_bfloat16*)xh, (__nv_bfloat16*)xl,
        Whp + 2 * WSZ, Wlp + 2 * WSZ, bv, (float*)vbuf, 1);

    // 3) KV accumulation (split + deterministic reduce)
    kv_partial_kernel<<<dim3(KV_CHUNKS, NHEADS, BATCH), 256>>>((const float*)kphi, (const float*)vbuf,
                                                               (float*)kvp, (float*)ksp);
    kv_reduce_kernel<<<BATCH * NHEADS, 256>>>((const float*)kvp, (const float*)ksp,
                                              (float*)kv, (float*)ks);

    // 4) numerator / denominator -> attn (hi/lo bf16)
    attn_kernel<<<dim3(SEQ / 64, NHEADS, BATCH), 256>>>((const float*)qphi, (const float*)kv,
                                                        (const float*)ks,
                                                        (__nv_bfloat16*)ahp, (__nv_bfloat16*)alp);

    // 5) output projection -> d_out
    gemm_split_kernel<<<ggrid, 256, GEMM_SMEM>>>((__nv_bfloat16*)ahp, (__nv_bfloat16*)alp,
        Whp + 3 * WSZ, Wlp + 3 * WSZ, bo, (float*)d_out, 1);
}

// round 17
// speedup vs baseline: 1.0265x; 1.0265x over previous
#include <cuda_runtime.h>
#include <cuda_bf16.h>
#include <cstdint>

// ---------------------------------------------------------------------------
// Problem constants
// ---------------------------------------------------------------------------
#define EMBED  1024
#define SEQ    4096
#define BATCH  4
#define NHEADS 16
#define HDIM   64
#define MTOT   (BATCH * SEQ)   // 16384
#define KV_CHUNKS 8
#define KV_CLEN   (SEQ / KV_CHUNKS)   // 512

// GEMM tiling: BM=128, BN=128, BK=32, mma.sync m16n8k16, double-buffered
#define BM 128
#define BN 128
#define BK 32
#define ROW_ELEMS (BK + 8)            // 40 bf16 (16B pad) -> stride 80B
#define RBYTES    (ROW_ELEMS * 2)     // 80
#define TILE_B    (BM * RBYTES)       // 10240 bytes per tile
#define BUF_B     (4 * TILE_B)        // Ah, Al, Bh, Bl = 40960
#define GEMM_SMEM (2 * BUF_B)         // 81920 bytes

// ---------------------------------------------------------------------------
// sm_80-era primitives only (harness compiles PTX at .target sm_103, which
// rejects all tcgen05/TMEM instructions -- verified by R6 ptxas failure).
// ---------------------------------------------------------------------------
__device__ __forceinline__ uint32_t smem_to_u32(const void* p) {
    uint32_t a;
    asm("{ .reg .u64 t; cvta.to.shared.u64 t, %1; cvt.u32.u64 %0, t; }" : "=r"(a) : "l"(p));
    return a;
}

__device__ __forceinline__ void cp_async16(uint32_t saddr, const void* gaddr) {
    asm volatile("cp.async.cg.shared.global [%0], [%1], 16;" :: "r"(saddr), "l"(gaddr));
}

// ldmatrix x4: four 8x8 b16 matrices; lanes 8i..8i+7 address matrix i rows.
__device__ __forceinline__ void ldmatrix_x4(uint32_t* r, uint32_t addr) {
    asm volatile("ldmatrix.sync.aligned.m8n8.x4.shared.b16 {%0,%1,%2,%3}, [%4];"
        : "=r"(r[0]), "=r"(r[1]), "=r"(r[2]), "=r"(r[3]) : "r"(addr));
}

// D += A * B   (m16n8k16, bf16 inputs, f32 accumulate)
__device__ __forceinline__ void mma16816(float* c, const uint32_t* a, const uint32_t* b) {
    asm volatile(
        "mma.sync.aligned.m16n8k16.row.col.f32.bf16.bf16.f32 "
        "{%0,%1,%2,%3}, {%4,%5,%6,%7}, {%8,%9}, {%0,%1,%2,%3};"
        : "+f"(c[0]), "+f"(c[1]), "+f"(c[2]), "+f"(c[3])
        : "r"(a[0]), "r"(a[1]), "r"(a[2]), "r"(a[3]), "r"(b[0]), "r"(b[1]));
}

// ---------------------------------------------------------------------------
// Device-global scratch (allocation-free rule: static globals only)
// ---------------------------------------------------------------------------
__device__ __nv_bfloat16 g_xh[MTOT * EMBED];
__device__ __nv_bfloat16 g_xl[MTOT * EMBED];
__device__ __nv_bfloat16 g_Wh[4][EMBED * EMBED];   // q,k,v,o
__device__ __nv_bfloat16 g_Wl[4][EMBED * EMBED];
__device__ float g_qphi[MTOT * EMBED];
__device__ float g_kphi[MTOT * EMBED];
__device__ float g_v[MTOT * EMBED];
__device__ float g_KVp[BATCH * NHEADS * KV_CHUNKS * HDIM * HDIM];
__device__ float g_Ksp[BATCH * NHEADS * KV_CHUNKS * HDIM];
__device__ float g_KV[BATCH * NHEADS * HDIM * HDIM];
__device__ float g_Ks[BATCH * NHEADS * HDIM];
__device__ __nv_bfloat16 g_ah[MTOT * EMBED];
__device__ __nv_bfloat16 g_al[MTOT * EMBED];

// ---------------------------------------------------------------------------
// fp32 -> (hi, lo) bf16 split, vectorized x4
// ---------------------------------------------------------------------------
__device__ __forceinline__ void split4(const float4 xv, uint2& ho, uint2& lo_) {
    float f[4] = {xv.x, xv.y, xv.z, xv.w};
    __nv_bfloat16 h[4], l[4];
#pragma unroll
    for (int m = 0; m < 4; ++m) {
        h[m] = __float2bfloat16(f[m]);
        l[m] = __float2bfloat16(f[m] - __bfloat162float(h[m]));
    }
    ho  = *reinterpret_cast<uint2*>(h);
    lo_ = *reinterpret_cast<uint2*>(l);
}

__global__ void split_kernel(const float4* __restrict__ src,
                             uint2* __restrict__ hi, uint2* __restrict__ lo, int n4) {
    int i = blockIdx.x * blockDim.x + threadIdx.x;
    if (i >= n4) return;
    uint2 h, l;
    split4(src[i], h, l);
    hi[i] = h;
    lo[i] = l;
}

// Splits all 4 weight matrices in one launch; blockIdx.y selects the matrix.
__global__ void split4_kernel(const float4* __restrict__ s0, const float4* __restrict__ s1,
                              const float4* __restrict__ s2, const float4* __restrict__ s3,
                              uint2* __restrict__ hi, uint2* __restrict__ lo, int n4) {
    int i = blockIdx.x * blockDim.x + threadIdx.x;
    if (i >= n4) return;
    const int w = blockIdx.y;
    const float4* src = (w == 0) ? s0 : (w == 1) ? s1 : (w == 2) ? s2 : s3;
    uint2 h, l;
    split4(src[i], h, l);
    hi[(long)w * n4 + i] = h;
    lo[(long)w * n4 + i] = l;
}

// ---------------------------------------------------------------------------
// Split-bf16 mma.sync GEMM: out[m,n] = sum_k A[m,k]*B[n,k] + bias[n]
// A = Ah+Al, B = Bh+Bl, drop lo*lo. CTA tile 128x128x32, 8 warps,
// warp tile 32(m) x 64(n). cp.async double-buffered SMEM, ldmatrix frags.
// mode 0: phi = elu+1 epilogue; mode 1: linear.
// ---------------------------------------------------------------------------
__global__ __launch_bounds__(256, 2)
void gemm_split_kernel(const __nv_bfloat16* __restrict__ Ah,
                       const __nv_bfloat16* __restrict__ Al,
                       const __nv_bfloat16* __restrict__ Bh,
                       const __nv_bfloat16* __restrict__ Bl,
                       const float* __restrict__ bias,
                       float* __restrict__ out,
                       int mode) {
    extern __shared__ char smem[];
    const uint32_t sb = smem_to_u32(smem);
    const int tid = threadIdx.x;
    const int wid = tid >> 5, lane = tid & 31;
    const int ntile = blockIdx.x, mtile = blockIdx.y;
    const long arow0 = (long)mtile * BM;
    const long brow0 = (long)ntile * BN;
    const int wm = wid & 3, wn = wid >> 2;   // 4 x 2 warp grid
    const int m0 = wm * 32, n0 = wn * 64;

    const __nv_bfloat16* gsrc[4] = {Ah, Al, Bh, Bl};

    float acc[2][8][4];
#pragma unroll
    for (int t = 0; t < 2; ++t)
#pragma unroll
        for (int u = 0; u < 8; ++u)
#pragma unroll
            for (int q = 0; q < 4; ++q) acc[t][u][q] = 0.f;

    auto issue_loads = [&](int buf, int ci) {
        const int k0 = ci * BK;
#pragma unroll
        for (int t = 0; t < 4; ++t) {
            const __nv_bfloat16* g = gsrc[t];
            const long row0 = (t < 2) ? arow0 : brow0;
            const uint32_t sdst = sb + buf * BUF_B + t * TILE_B;
#pragma unroll
            for (int j = 0; j < 2; ++j) {
                int s = tid + 256 * j;          // 0..511
                int r = s >> 2, c16 = s & 3;    // 128 rows x 4 x 16B
                cp_async16(sdst + r * RBYTES + c16 * 16,
                           g + (row0 + r) * EMBED + k0 + c16 * 8);
            }
        }
        asm volatile("cp.async.commit_group;" ::: "memory");
    };

    auto compute = [&](int buf) {
        const uint32_t b0 = sb + buf * BUF_B;
        const int q = lane >> 3, rr = lane & 7;
#pragma unroll
        for (int ks = 0; ks < 2; ++ks) {
            const int kb0 = ks * 32;            // 16 k-elems = 32 bytes per step
            uint32_t ah[2][4], al[2][4];
            // A frags: x4 matrices = (rows 0-7,k0-7),(8-15,k0-7),(0-7,k8-15),(8-15,k8-15)
#pragma unroll
            for (int t = 0; t < 2; ++t) {
                const uint32_t addr = b0 +
                    (uint32_t)((m0 + t * 16 + rr + (q & 1) * 8) * RBYTES + kb0 + (q >> 1) * 16);
                ldmatrix_x4(ah[t], addr);
                ldmatrix_x4(al[t], addr + TILE_B);
            }
            uint32_t bh[8][2], bl[8][2];
            // B frags: one x4 covers 2 n-groups: (u,k0),(u,k8),(u+1,k0),(u+1,k8)
#pragma unroll
            for (int up = 0; up < 4; ++up) {
                const int u = up * 2;
                const uint32_t addr = b0 + 2 * TILE_B +
                    (uint32_t)((n0 + u * 8 + (q >> 1) * 8 + rr) * RBYTES + kb0 + (q & 1) * 16);
                uint32_t tmp[4];
                ldmatrix_x4(tmp, addr);
                bh[u][0] = tmp[0]; bh[u][1] = tmp[1];
                bh[u + 1][0] = tmp[2]; bh[u + 1][1] = tmp[3];
                ldmatrix_x4(tmp, addr + TILE_B);
                bl[u][0] = tmp[0]; bl[u][1] = tmp[1];
                bl[u + 1][0] = tmp[2]; bl[u + 1][1] = tmp[3];
            }
            // Three passes over the 16 accumulators: consecutive HMMAs hit
            // distinct acc registers (dependency distance 16, not 1).
#pragma unroll
            for (int t = 0; t < 2; ++t)
#pragma unroll
                for (int u = 0; u < 8; ++u)
                    mma16816(acc[t][u], ah[t], bh[u]);
#pragma unroll
            for (int t = 0; t < 2; ++t)
#pragma unroll
                for (int u = 0; u < 8; ++u)
                    mma16816(acc[t][u], ah[t], bl[u]);
#pragma unroll
            for (int t = 0; t < 2; ++t)
#pragma unroll
                for (int u = 0; u < 8; ++u)
                    mma16816(acc[t][u], al[t], bh[u]);
        }
    };

    issue_loads(0, 0);
#pragma unroll 1
    for (int c = 0; c < EMBED / BK; ++c) {
        if (c + 1 < EMBED / BK) {
            issue_loads((c + 1) & 1, c + 1);
            asm volatile("cp.async.wait_group 1;" ::: "memory");
        } else {
            asm volatile("cp.async.wait_group 0;" ::: "memory");
        }
        __syncthreads();
        compute(c & 1);
        __syncthreads();
    }

    // Epilogue: bias + optional phi, 8B vectorized stores.
#pragma unroll
    for (int t = 0; t < 2; ++t) {
        const long row_a = arow0 + m0 + t * 16 + (lane >> 2);
        const long row_b = row_a + 8;
#pragma unroll
        for (int u = 0; u < 8; ++u) {
            const int col = ntile * BN + n0 + u * 8 + (lane & 3) * 2;
            const float2 bv = *reinterpret_cast<const float2*>(bias + col);
            float v0 = acc[t][u][0] + bv.x;
            float v1 = acc[t][u][1] + bv.y;
            float v2 = acc[t][u][2] + bv.x;
            float v3 = acc[t][u][3] + bv.y;
            if (mode == 0) {
                v0 = (v0 > 0.f) ? (v0 + 1.f) : __expf(v0);
                v1 = (v1 > 0.f) ? (v1 + 1.f) : __expf(v1);
                v2 = (v2 > 0.f) ? (v2 + 1.f) : __expf(v2);
                v3 = (v3 > 0.f) ? (v3 + 1.f) : __expf(v3);
            }
            float2 o01 = {v0, v1}, o23 = {v2, v3};
            *reinterpret_cast<float2*>(out + row_a * EMBED + col) = o01;
            *reinterpret_cast<float2*>(out + row_b * EMBED + col) = o23;
        }
    }
}

// ---------------------------------------------------------------------------
// KV partial: per (chunk, h, b) block accumulates KV[64,64] and Ksum[64]
// over KV_CLEN sequence positions (fp32 SIMT; deterministic, no atomics)
// ---------------------------------------------------------------------------
__global__ __launch_bounds__(256)
void kv_partial_kernel(const float* __restrict__ kphi, const float* __restrict__ v,
                       float* __restrict__ KVp, float* __restrict__ Ksp) {
    __shared__ float ks_[64][64];
    __shared__ float vs_[64][64];
    const int tid = threadIdx.x;
    const int chunk = blockIdx.x, h = blockIdx.y, b = blockIdx.z;
    const int dq = tid >> 4, eq = tid & 15;
    float acc[4][4];
#pragma unroll
    for (int i = 0; i < 4; ++i)
#pragma unroll
        for (int j = 0; j < 4; ++j) acc[i][j] = 0.f;
    float ksum[4] = {0.f, 0.f, 0.f, 0.f};
    const long base = ((long)b * SEQ + chunk * KV_CLEN) * EMBED + h * HDIM;
    for (int s0 = 0; s0 < KV_CLEN; s0 += 64) {
#pragma unroll
        for (int j = 0; j < 4; ++j) {
            int idx = tid + 256 * j;
            int r = idx >> 4, c4 = idx & 15;
            *reinterpret_cast<float4*>(&ks_[r][c4 * 4]) =
                *(reinterpret_cast<const float4*>(kphi + base + (long)(s0 + r) * EMBED) + c4);
            *reinterpret_cast<float4*>(&vs_[r][c4 * 4]) =
                *(reinterpret_cast<const float4*>(v + base + (long)(s0 + r) * EMBED) + c4);
        }
        __syncthreads();
#pragma unroll 2
        for (int ss = 0; ss < 64; ++ss) {
            float4 kk = *reinterpret_cast<float4*>(&ks_[ss][dq * 4]);
            float4 vv = *reinterpret_cast<float4*>(&vs_[ss][eq * 4]);
            float kd[4] = {kk.x, kk.y, kk.z, kk.w};
            float ve[4] = {vv.x, vv.y, vv.z, vv.w};
#pragma unroll
            for (int i = 0; i < 4; ++i) {
#pragma unroll
                for (int j = 0; j < 4; ++j) acc[i][j] += kd[i] * ve[j];
                ksum[i] += kd[i];
            }
        }
        __syncthreads();
    }
    const long ob = (((long)b * NHEADS + h) * KV_CHUNKS + chunk) * (HDIM * HDIM);
#pragma unroll
    for (int i = 0; i < 4; ++i)
#pragma unroll
        for (int j = 0; j < 4; ++j)
            KVp[ob + (dq * 4 + i) * HDIM + eq * 4 + j] = acc[i][j];
    if (eq == 0) {
        const long kb = (((long)b * NHEADS + h) * KV_CHUNKS + chunk) * HDIM;
#pragma unroll
        for (int i = 0; i < 4; ++i) Ksp[kb + dq * 4 + i] = ksum[i];
    }
}

__global__ void kv_reduce_kernel(const float* __restrict__ KVp, const float* __restrict__ Ksp,
                                 float* __restrict__ KV, float* __restrict__ Ks) {
    const int bh = blockIdx.x, tid = threadIdx.x;
    for (int i = tid; i < HDIM * HDIM; i += 256) {
        float s = 0.f;
#pragma unroll
        for (int c = 0; c < KV_CHUNKS; ++c) s += KVp[((long)bh * KV_CHUNKS + c) * (HDIM * HDIM) + i];
        KV[(long)bh * (HDIM * HDIM) + i] = s;
    }
    if (tid < HDIM) {
        float s = 0.f;
#pragma unroll
        for (int c = 0; c < KV_CHUNKS; ++c) s += Ksp[((long)bh * KV_CHUNKS + c) * HDIM + tid];
        Ks[(long)bh * HDIM + tid] = s;
    }
}

// ---------------------------------------------------------------------------
// Attention: out[s,e] = (q_phi[s,:] . KV[:,e]) / (q_phi[s,:] . Ksum + eps)
// 64-row seq tile per block; writes attn as hi/lo bf16 for the final GEMM.
// ---------------------------------------------------------------------------
__global__ __launch_bounds__(256)
void attn_kernel(const float* __restrict__ qphi, const float* __restrict__ KV,
                 const float* __restrict__ Ksum,
                 __nv_bfloat16* __restrict__ ah, __nv_bfloat16* __restrict__ al) {
    __shared__ float qs[64][68];
    __shared__ float kvs[64][64];
    __shared__ float kss[64];
    __shared__ float den[64];
    const int tid = threadIdx.x;
    const int st = blockIdx.x, h = blockIdx.y, b = blockIdx.z;
    const int bh = b * NHEADS + h;
    const long qbase = ((long)b * SEQ + st * 64) * EMBED + h * HDIM;
#pragma unroll
    for (int j = 0; j < 4; ++j) {
        int idx = tid + 256 * j;
        int r = idx >> 4, c4 = idx & 15;
        *reinterpret_cast<float4*>(&qs[r][c4 * 4]) =
            *(reinterpret_cast<const float4*>(qphi + qbase + (long)r * EMBED) + c4);
        *reinterpret_cast<float4*>(&kvs[r][c4 * 4]) =
            *(reinterpret_cast<const float4*>(KV + (long)bh * (HDIM * HDIM) + r * HDIM) + c4);
    }
    if (tid < 64) kss[tid] = Ksum[(long)bh * HDIM + tid];
    __syncthreads();
    if (tid < 64) {
        float s = 0.f;
#pragma unroll 8
        for (int d = 0; d < 64; ++d) s += qs[tid][d] * kss[d];
        den[tid] = s + 1e-6f;
    }
    __syncthreads();
    const int e = tid & 63, g = tid >> 6;
    float acc[16];
#pragma unroll
    for (int r = 0; r < 16; ++r) acc[r] = 0.f;
    for (int d = 0; d < 64; ++d) {
        float kd = kvs[d][e];
#pragma unroll
        for (int r = 0; r < 16; ++r) acc[r] += qs[g * 16 + r][d] * kd;
    }
#pragma unroll
    for (int r = 0; r < 16; ++r) {
        const int sl = g * 16 + r;
        float val = acc[r] / den[sl];
        const long oi = ((long)b * SEQ + st * 64 + sl) * EMBED + h * HDIM + e;
        __nv_bfloat16 hv = __float2bfloat16(val);
        ah[oi] = hv;
        al[oi] = __float2bfloat16(val - __bfloat162float(hv));
    }
}

// ---------------------------------------------------------------------------
// Launch
// ---------------------------------------------------------------------------
extern "C" void kernel_launch(void* const* d_in, const int* in_sizes, int n_in,
                              void* d_out, int out_size) {
    (void)in_sizes; (void)n_in; (void)out_size;
    const float* x  = (const float*)d_in[0];
    const float* Wq = (const float*)d_in[1];
    const float* bq = (const float*)d_in[2];
    const float* Wk = (const float*)d_in[3];
    const float* bk = (const float*)d_in[4];
    const float* Wv = (const float*)d_in[5];
    const float* bv = (const float*)d_in[6];
    const float* Wo = (const float*)d_in[7];
    const float* bo = (const float*)d_in[8];

    void *xh, *xl, *wh, *wl, *qphi, *kphi, *vbuf, *kvp, *ksp, *kv, *ks, *ahp, *alp;
    cudaGetSymbolAddress(&xh, g_xh);   cudaGetSymbolAddress(&xl, g_xl);
    cudaGetSymbolAddress(&wh, g_Wh);   cudaGetSymbolAddress(&wl, g_Wl);
    cudaGetSymbolAddress(&qphi, g_qphi); cudaGetSymbolAddress(&kphi, g_kphi);
    cudaGetSymbolAddress(&vbuf, g_v);
    cudaGetSymbolAddress(&kvp, g_KVp); cudaGetSymbolAddress(&ksp, g_Ksp);
    cudaGetSymbolAddress(&kv, g_KV);   cudaGetSymbolAddress(&ks, g_Ks);
    cudaGetSymbolAddress(&ahp, g_ah);  cudaGetSymbolAddress(&alp, g_al);

    __nv_bfloat16* Whp = (__nv_bfloat16*)wh;
    __nv_bfloat16* Wlp = (__nv_bfloat16*)wl;
    const int WSZ = EMBED * EMBED;

    cudaFuncSetAttribute(gemm_split_kernel, cudaFuncAttributeMaxDynamicSharedMemorySize, GEMM_SMEM);

    // 1) hi/lo splits: x (1 launch), all 4 weights (1 launch)
    {
        int n4 = MTOT * EMBED / 4;
        split_kernel<<<(n4 + 255) / 256, 256>>>((const float4*)x, (uint2*)xh, (uint2*)xl, n4);
        int w4 = WSZ / 4;
        split4_kernel<<<dim3((w4 + 255) / 256, 4), 256>>>(
            (const float4*)Wq, (const float4*)Wk, (const float4*)Wv, (const float4*)Wo,
            (uint2*)wh, (uint2*)wl, w4);
    }

    dim3 ggrid(EMBED / BN, MTOT / BM);   // (8, 128)
    // 2) Q/K/V projections (phi fused for q, k)
    gemm_split_kernel<<<ggrid, 256, GEMM_SMEM>>>((__nv_bfloat16*)xh, (__nv_bfloat16*)xl,
        Whp + 0 * WSZ, Wlp + 0 * WSZ, bq, (float*)qphi, 0);
    gemm_split_kernel<<<ggrid, 256, GEMM_SMEM>>>((__nv_bfloat16*)xh, (__nv_bfloat16*)xl,
        Whp + 1 * WSZ, Wlp + 1 * WSZ, bk, (float*)kphi, 0);
    gemm_split_kernel<<<ggrid, 256, GEMM_SMEM>>>((__nv_bfloat16*)xh, (__nv_bfloat16*)xl,
        Whp + 2 * WSZ, Wlp + 2 * WSZ, bv, (float*)vbuf, 1);

    // 3) KV accumulation (split + deterministic reduce)
    kv_partial_kernel<<<dim3(KV_CHUNKS, NHEADS, BATCH), 256>>>((const float*)kphi, (const float*)vbuf,
                                                               (float*)kvp, (float*)ksp);
    kv_reduce_kernel<<<BATCH * NHEADS, 256>>>((const float*)kvp, (const float*)ksp,
                                              (float*)kv, (float*)ks);

    // 4) numerator / denominator -> attn (hi/lo bf16)
    attn_kernel<<<dim3(SEQ / 64, NHEADS, BATCH), 256>>>((const float*)qphi, (const float*)kv,
                                                        (const float*)ks,
                                                        (__nv_bfloat16*)ahp, (__nv_bfloat16*)alp);

    // 5) output projection -> d_out
    gemm_split_kernel<<<ggrid, 256, GEMM_SMEM>>>((__nv_bfloat16*)ahp, (__nv_bfloat16*)alp,
        Whp + 3 * WSZ, Wlp + 3 * WSZ, bo, (float*)d_out, 1);
}